// round 4
// baseline (speedup 1.0000x reference)
#include <cuda_runtime.h>

#define FULL_MASK 0xffffffffu
#define KV 8   // float4 vectors per thread

// out[j] = x[j - offset] for 0 <= j-offset < n else 0; offset from device scalars.
// Warp tile: 256 consecutive output vectors per warp; each thread owns KV=8
// vectors at lane-contiguous addresses (fully coalesced LDG.128/STG.128,
// 8 front-batched independent loads = 128B in flight per thread).
// Misalignment r = offset & 3 repaired with minimal warp shuffles.
// n % 4 == 0 so whole-vector zero predication is exact at the boundaries.

__global__ void __launch_bounds__(256)
shift_warptile8(const float4* __restrict__ x4,
                const float*  __restrict__ xs,
                const float*  __restrict__ w_row,
                const float*  __restrict__ w_col,
                int row_length, int n,
                float4* __restrict__ out4)
{
    const int nv = n >> 2;
    const int offset = (int)(w_row[0] + (float)row_length * w_col[0]);
    const int r = offset & 3;
    const int m = (offset - r) >> 2;              // floor(offset/4)

    const int warp_id = (blockIdx.x * blockDim.x + threadIdx.x) >> 5;
    const int lane    = threadIdx.x & 31;
    const int wbase   = warp_id << (5 + 3);       // 256 vectors per warp
    const int g0      = wbase + lane;

    // Front-batched independent aligned loads (MLP = 8).
    float4 v[KV];
#pragma unroll
    for (int k = 0; k < KV; k++) {
        const int g  = g0 + (k << 5);
        const int sv = g - m;
        float4 t = make_float4(0.f, 0.f, 0.f, 0.f);
        if (g < nv && sv >= 0 && sv < nv) t = __ldcs(x4 + sv);
        v[k] = t;
    }

    if (r == 0) {
#pragma unroll
        for (int k = 0; k < KV; k++) {
            const int g = g0 + (k << 5);
            if (g < nv) __stcs(out4 + g, v[k]);
        }
        return;
    }

    // Boundary words for lane 0, k = 0: words (4-r..3) of vector (wbase-m-1).
    float e_y = 0.f, e_z = 0.f, e_w = 0.f;
    if (lane == 0) {
        const int ebase = 4 * (wbase - m) - 4;
        if (r >= 3) { int i = ebase + 1; if (i >= 0 && i < n) e_y = __ldcs(xs + i); }
        if (r >= 2) { int i = ebase + 2; if (i >= 0 && i < n) e_z = __ldcs(xs + i); }
        /* r>=1 */ { int i = ebase + 3; if (i >= 0 && i < n) e_w = __ldcs(xs + i); }
    }

    // Previous-vector word: lane>0 -> lane-1's v[k];
    // lane0,k>0 -> lane31's v[k-1]; lane0,k==0 -> boundary scalar.
#define PREVW(comp, k, evar, dst)                                              \
    do {                                                                       \
        float _up  = __shfl_up_sync(FULL_MASK, v[k].comp, 1);                  \
        float _b31 = __shfl_sync(FULL_MASK, (k) > 0 ? v[(k)>0?(k)-1:0].comp    \
                                                    : 0.f, 31);                \
        dst = (lane == 0) ? ((k) > 0 ? _b31 : (evar)) : _up;                   \
    } while (0)

#pragma unroll
    for (int k = 0; k < KV; k++) {
        float pw, pz, py;
        PREVW(w, k, e_w, pw);
        float4 o;
        if (r == 1) {
            o = make_float4(pw, v[k].x, v[k].y, v[k].z);
        } else if (r == 2) {
            PREVW(z, k, e_z, pz);
            o = make_float4(pz, pw, v[k].x, v[k].y);
        } else {
            PREVW(z, k, e_z, pz);
            PREVW(y, k, e_y, py);
            o = make_float4(py, pz, pw, v[k].x);
        }
        const int g = g0 + (k << 5);
        if (g < nv) __stcs(out4 + g, o);
    }
#undef PREVW
}

extern "C" void kernel_launch(void* const* d_in, const int* in_sizes, int n_in,
                              void* d_out, int out_size)
{
    const float* x     = (const float*)d_in[0];
    const float* w_row = (const float*)d_in[1];
    const float* w_col = (const float*)d_in[2];

    const int n = in_sizes[0];
    int row_length = 1;
    while ((long long)row_length * row_length < (long long)n) row_length <<= 1;

    const int nv = n >> 2;                        // output float4 count
    const int vec_per_warp = 32 * KV;             // 256
    const int warps = (nv + vec_per_warp - 1) / vec_per_warp;
    const int threads = 256;
    const int blocks = (warps * 32 + threads - 1) / threads;

    shift_warptile8<<<blocks, threads>>>((const float4*)x, x, w_row, w_col,
                                         row_length, n, (float4*)d_out);
}